// round 17
// baseline (speedup 1.0000x reference)
#include <cuda_runtime.h>
#include <cstdint>

#define GS     16
#define NPAIR  136          // 16*17/2 lower-triangular pairs
#define NACC   152          // 136 pair sums + 16 channel sums
#define GROUPS 32
#define BATCH  32
#define HW     3136         // 56*56
#define HW4    784          // HW/4 (float4 units)
#define HALF4  392          // HW4/2
#define CH     512
#define NPART  64           // partial blocks per group: 32 batches x 2 halves

typedef unsigned long long ull;

static __device__ float d_part[GROUPS][NPART][NACC]; // per-block partial sums
static __device__ float d_Linv[GROUPS][NPAIR];       // packed lower-tri Linv
static __device__ float d_bias[CH];                  // Linv @ mean

// ---- packed f32x2 helpers (Blackwell) --------------------------------------
__device__ __forceinline__ void fma2(ull& d, ull a, ull b) {
    asm("fma.rn.f32x2 %0, %1, %2, %0;" : "+l"(d) : "l"(a), "l"(b));
}
__device__ __forceinline__ void add2(ull& d, ull a) {
    asm("add.rn.f32x2 %0, %0, %1;" : "+l"(d) : "l"(a));
}
__device__ __forceinline__ float unpack_add(ull v) {
    float lo, hi;
    asm("mov.b64 {%0,%1}, %2;" : "=f"(lo), "=f"(hi) : "l"(v));
    return lo + hi;
}

struct V2 { ull a, b; };   // one float4 = two packed f32x2 halves

__device__ __forceinline__ V2 ld_v2(const float4* p) {
    V2 v;
    asm("ld.global.nc.v2.u64 {%0,%1}, [%2];" : "=l"(v.a), "=l"(v.b) : "l"(p));
    return v;
}

// ---------------------------------------------------------------------------
// Stats v3c: proven v3b core (12 warps, 4 roles x 96 lanes), tile split into
// 2 position-halves (grid 2048 -> 13.8 short waves, smaller tail/spread), and
// ATOMIC-FREE: block writes its partials to d_part (no zero kernel needed).
//   role 0: diag pairs in ch0-7   (36 packed acc + 8 packed sums)
//   role 1: diag pairs in ch8-15
//   role 2: cross i in 8-15, j in 0-3  (32 packed acc)
//   role 3: cross i in 8-15, j in 4-7
__global__ void __launch_bounds__(384) stats_kernel(const float* __restrict__ x) {
    const int g    = blockIdx.x & 31;
    const int b    = (blockIdx.x >> 5) & 31;
    const int half = blockIdx.x >> 10;
    const float4* in = (const float4*)(x + ((size_t)b * CH + (size_t)g * GS) * HW);

    const int tid  = threadIdx.x;
    const int wid  = tid >> 5;
    const int lane = tid & 31;
    const int role = wid / 3;              // 0..3
    const int id   = tid - role * 96;      // 0..95 within role
    const int beg  = half * HALF4;
    const int end  = beg + HALF4;

    __shared__ float red[12][44];

    if (role < 2) {
        // ---------------- diagonal roles ------------------------------------
        const int co = role * 8;
        ull acc[36], sum[8];
#pragma unroll
        for (int k = 0; k < 36; k++) acc[k] = 0ull;
#pragma unroll
        for (int k = 0; k < 8; k++) sum[k] = 0ull;

        for (int pos = beg + id; pos < end; pos += 96) {
            V2 v[8];
#pragma unroll
            for (int c = 0; c < 8; c++) v[c] = ld_v2(in + (size_t)(co + c) * HW4 + pos);
#pragma unroll
            for (int i = 0; i < 8; i++) {
#pragma unroll
                for (int j = 0; j <= i; j++) {
                    const int k = i * (i + 1) / 2 + j;
                    fma2(acc[k], v[i].a, v[j].a);
                    fma2(acc[k], v[i].b, v[j].b);
                }
                add2(sum[i], v[i].a);
                add2(sum[i], v[i].b);
            }
        }

        float r[44];
#pragma unroll
        for (int k = 0; k < 36; k++) r[k] = unpack_add(acc[k]);
#pragma unroll
        for (int k = 0; k < 8; k++)  r[36 + k] = unpack_add(sum[k]);
#pragma unroll
        for (int k = 0; k < 44; k++) {
#pragma unroll
            for (int off = 16; off > 0; off >>= 1)
                r[k] += __shfl_xor_sync(0xffffffffu, r[k], off);
        }
        if (lane == 0) {
#pragma unroll
            for (int k = 0; k < 44; k++) red[wid][k] = r[k];
        }
    } else {
        // ---------------- cross roles: i in 8-15, j in jo..jo+3 -------------
        const int jo = (role - 2) * 4;
        ull acc[32];
#pragma unroll
        for (int k = 0; k < 32; k++) acc[k] = 0ull;

        for (int pos = beg + id; pos < end; pos += 96) {
            V2 u[8], w[4];
#pragma unroll
            for (int c = 0; c < 8; c++) u[c] = ld_v2(in + (size_t)(8 + c) * HW4 + pos);
#pragma unroll
            for (int c = 0; c < 4; c++) w[c] = ld_v2(in + (size_t)(jo + c) * HW4 + pos);
#pragma unroll
            for (int i = 0; i < 8; i++)
#pragma unroll
                for (int j = 0; j < 4; j++) {
                    const int k = i * 4 + j;
                    fma2(acc[k], u[i].a, w[j].a);
                    fma2(acc[k], u[i].b, w[j].b);
                }
        }

        float r[32];
#pragma unroll
        for (int k = 0; k < 32; k++) r[k] = unpack_add(acc[k]);
#pragma unroll
        for (int k = 0; k < 32; k++) {
#pragma unroll
            for (int off = 16; off > 0; off >>= 1)
                r[k] += __shfl_xor_sync(0xffffffffu, r[k], off);
        }
        if (lane == 0) {
#pragma unroll
            for (int k = 0; k < 32; k++) red[wid][k] = r[k];
        }
    }
    __syncthreads();

    // combine the 3 warps of each role and store partials (no atomics).
    // entries: [0,44) diag0, [44,88) diag1, [88,120) cross0, [120,152) cross1
    const int p = b * 2 + half;
    if (tid < 152) {
        int w0, e;
        if (tid < 44)       { w0 = 0; e = tid; }
        else if (tid < 88)  { w0 = 3; e = tid - 44; }
        else if (tid < 120) { w0 = 6; e = tid - 88; }
        else                { w0 = 9; e = tid - 120; }
        const float s = red[w0][e] + red[w0 + 1][e] + red[w0 + 2][e];

        int idx;
        if (tid < 88) {
            const int co = (tid < 44) ? 0 : 8;
            if (e < 36) {
                int i = 0;
                while ((i + 1) * (i + 2) / 2 <= e) i++;
                const int j = e - i * (i + 1) / 2;
                const int gi = co + i, gj = co + j;
                idx = gi * (gi + 1) / 2 + gj;
            } else {
                idx = NPAIR + co + (e - 36);
            }
        } else {
            const int jo = (tid < 120) ? 0 : 4;
            const int i = e >> 2, j = e & 3;
            const int gi = 8 + i, gj = jo + j;
            idx = gi * (gi + 1) / 2 + gj;
        }
        d_part[g][p][idx] = s;
    }
}

// ---------------------------------------------------------------------------
// Solve: one block per group, 128 threads. Phase 1: reduce 64 partials into
// smem (atomic-free). Phase 2: 16 threads do cov->Cholesky->inv(L)->bias, fp64.
__global__ void __launch_bounds__(128) solve_kernel() {
    const int g = blockIdx.x;
    const int t = threadIdx.x;

    __shared__ float accs[NACC];
    for (int e = t; e < NACC; e += 128) {
        float s = 0.f;
#pragma unroll 8
        for (int p = 0; p < NPART; p++) s += d_part[g][p][e];
        accs[e] = s;
    }
    __syncthreads();

    if (t >= GS) return;
    __shared__ double P[GS][GS + 1];
    __shared__ double L[GS][GS + 1];
    __shared__ double V[GS][GS + 1];
    __shared__ double m[GS];

    const double Nd   = (double)BATCH * (double)HW;
    const double EPSd = 1e-3;
    const unsigned MASK = 0xffffu;

    m[t] = (double)accs[NPAIR + t] / Nd;
    __syncwarp(MASK);

    for (int j = 0; j < GS; j++) {
        const int i_ = t > j ? t : j, j_ = t > j ? j : t;
        double c = (double)accs[i_ * (i_ + 1) / 2 + j_] / Nd - m[t] * m[j];
        c *= (1.0 - EPSd);
        if (t == j) c += EPSd;
        P[t][j] = c;
    }
    __syncwarp(MASK);

    for (int j = 0; j < GS; j++) {
        if (t == j) {
            double s = P[j][j];
            for (int k = 0; k < j; k++) s -= L[j][k] * L[j][k];
            L[j][j] = sqrt(s);
        }
        __syncwarp(MASK);
        if (t > j) {
            double s = P[t][j];
            for (int k = 0; k < j; k++) s -= L[t][k] * L[j][k];
            L[t][j] = s / L[j][j];
        }
        __syncwarp(MASK);
    }

    V[t][t] = 1.0 / L[t][t];
    for (int i = t + 1; i < GS; i++) {
        double s = 0.0;
        for (int k = t; k < i; k++) s += L[i][k] * V[k][t];
        V[i][t] = -s / L[i][i];
    }
    __syncwarp(MASK);

    double bsum = 0.0;
    for (int j = 0; j <= t; j++) {
        d_Linv[g][t * (t + 1) / 2 + j] = (float)V[t][j];
        bsum += V[t][j] * m[j];
    }
    d_bias[g * GS + t] = (float)bsum;
}

// ---------------------------------------------------------------------------
// Apply: proven float4/256-thr/2-per-SM core, tile split into 2 position
// halves (grid 2048) for finer waves / smaller quantization tail.
__global__ void __launch_bounds__(256, 2) apply_kernel(const float* __restrict__ x,
                                                       float* __restrict__ out) {
    const int half = blockIdx.x >> 10;
    const int bg   = blockIdx.x & 1023;
    const int g = bg & 31;
    const int b = bg >> 5;

    __shared__ float Ls[NPAIR];
    __shared__ float bs[GS];
    if (threadIdx.x < NPAIR) Ls[threadIdx.x] = d_Linv[g][threadIdx.x];
    if (threadIdx.x < GS)    bs[threadIdx.x] = d_bias[g * GS + threadIdx.x];
    __syncthreads();

    const size_t off = ((size_t)b * CH + (size_t)g * GS) * HW;
    const float4* in = (const float4*)(x + off);
    float4*       op = (float4*)(out + off);

    const int beg = half * HALF4;
    const int end = beg + HALF4;

    for (int pos = beg + threadIdx.x; pos < end; pos += 256) {
        float4 v[GS];
#pragma unroll
        for (int c = 0; c < GS; c++) v[c] = in[(size_t)c * HW4 + pos];
#pragma unroll
        for (int i = 0; i < GS; i++) {
            const float bias = bs[i];
            float4 a;
            a.x = -bias; a.y = -bias; a.z = -bias; a.w = -bias;
#pragma unroll
            for (int j = 0; j <= i; j++) {
                const float f = Ls[i * (i + 1) / 2 + j];
                a.x = fmaf(f, v[j].x, a.x);
                a.y = fmaf(f, v[j].y, a.y);
                a.z = fmaf(f, v[j].z, a.z);
                a.w = fmaf(f, v[j].w, a.w);
            }
            __stcs(&op[(size_t)i * HW4 + pos], a);
        }
    }
}

// ---------------------------------------------------------------------------
extern "C" void kernel_launch(void* const* d_in, const int* in_sizes, int n_in,
                              void* d_out, int out_size) {
    const float* x   = (const float*)d_in[0];
    float*       out = (float*)d_out;

    stats_kernel<<<GROUPS * BATCH * 2, 384>>>(x);
    solve_kernel<<<GROUPS, 128>>>();
    apply_kernel<<<GROUPS * BATCH * 2, 256>>>(x, out);
}